// round 2
// baseline (speedup 1.0000x reference)
#include <cuda_runtime.h>
#include <cstdint>

#define NENT 100000
#define NEDGE 2000000
#define DV 128

// Scratch: h (normalized embeddings) and pre (pre-GEMM aggregation), as float4 rows [N][32]
__device__ float4 g_h[NENT * 32];
__device__ float4 g_pre[NENT * 32];

// ---------------------------------------------------------------------------
// Kernel 1: L2-normalize ent_emb -> g_h, and zero g_pre. Warp per node.
// ---------------------------------------------------------------------------
__global__ void k_norm(const float4* __restrict__ ent) {
    int gw = (blockIdx.x * blockDim.x + threadIdx.x) >> 5;
    int lane = threadIdx.x & 31;
    if (gw >= NENT) return;
    float4 v = ent[gw * 32 + lane];
    float s = v.x * v.x + v.y * v.y + v.z * v.z + v.w * v.w;
#pragma unroll
    for (int o = 16; o; o >>= 1) s += __shfl_xor_sync(0xffffffffu, s, o);
    float inv = 1.0f / fmaxf(sqrtf(s), 1e-12f);
    v.x *= inv; v.y *= inv; v.z *= inv; v.w *= inv;
    g_h[gw * 32 + lane] = v;
    g_pre[gw * 32 + lane] = make_float4(0.f, 0.f, 0.f, 0.f);
}

// ---------------------------------------------------------------------------
// Kernel 2: per-edge scatter: pre[dst] += norm * (h[src] + rel[etype]).
// Warp per edge; vector red (v4.f32) to quarter the L2 atomic op count.
// ---------------------------------------------------------------------------
__global__ void k_edge(const float4* __restrict__ rel,
                       const float* __restrict__ enorm,
                       const int* __restrict__ src,
                       const int* __restrict__ dst,
                       const int* __restrict__ et) {
    int e = (blockIdx.x * blockDim.x + threadIdx.x) >> 5;
    int lane = threadIdx.x & 31;
    if (e >= NEDGE) return;
    int s = src[e];
    int d = dst[e];
    int t = et[e];
    float w = enorm[e];
    float4 hv = g_h[s * 32 + lane];
    float4 rv = rel[t * 32 + lane];
    float4 m;
    m.x = (hv.x + rv.x) * w;
    m.y = (hv.y + rv.y) * w;
    m.z = (hv.z + rv.z) * w;
    m.w = (hv.w + rv.w) * w;
    float* p = (float*)(g_pre + (size_t)d * 32 + lane);
    asm volatile("red.global.add.v4.f32 [%0], {%1,%2,%3,%4};"
                 :: "l"(p), "f"(m.x), "f"(m.y), "f"(m.z), "f"(m.w)
                 : "memory");
}

// ---------------------------------------------------------------------------
// Kernel 3: per-node fused epilogue.
//   h_cur = pre @ Wn + h @ Ws ; rrelu ; gate = sigmoid(h_cur @ Wg + b)
//   out = gate*h_cur + (1-gate)*his
// Warp per node, all three 128x128 weight matrices in smem (192 KB),
// persistent grid (1 block/SM).
// ---------------------------------------------------------------------------
__global__ void __launch_bounds__(512, 1)
k_node(const float4* __restrict__ his,
       const float4* __restrict__ bias,
       const float4* __restrict__ Wn,
       const float4* __restrict__ Ws,
       const float4* __restrict__ Wg,
       float4* __restrict__ out) {
    extern __shared__ float4 smw[];
    float4* sWn = smw;           // 4096 float4 = 64 KB
    float4* sWs = sWn + 4096;
    float4* sWg = sWs + 4096;

    for (int i = threadIdx.x; i < 4096; i += blockDim.x) {
        sWn[i] = Wn[i];
        sWs[i] = Ws[i];
        sWg[i] = Wg[i];
    }
    __syncthreads();

    const int lane = threadIdx.x & 31;
    const int wid = threadIdx.x >> 5;
    const int nwarps = blockDim.x >> 5;
    const float4 bb = bias[lane];
    const float SL = 0.22916666666666666f;  // rrelu eval-mode slope

    for (int n = blockIdx.x * nwarps + wid; n < NENT; n += gridDim.x * nwarps) {
        float4 p = g_pre[n * 32 + lane];
        float4 hv = g_h[n * 32 + lane];
        float4 acc = make_float4(0.f, 0.f, 0.f, 0.f);

#pragma unroll 4
        for (int kq = 0; kq < 32; kq++) {
            float pb[4], hb[4];
            pb[0] = __shfl_sync(0xffffffffu, p.x, kq);
            pb[1] = __shfl_sync(0xffffffffu, p.y, kq);
            pb[2] = __shfl_sync(0xffffffffu, p.z, kq);
            pb[3] = __shfl_sync(0xffffffffu, p.w, kq);
            hb[0] = __shfl_sync(0xffffffffu, hv.x, kq);
            hb[1] = __shfl_sync(0xffffffffu, hv.y, kq);
            hb[2] = __shfl_sync(0xffffffffu, hv.z, kq);
            hb[3] = __shfl_sync(0xffffffffu, hv.w, kq);
#pragma unroll
            for (int i = 0; i < 4; i++) {
                int k = kq * 4 + i;
                float4 w1 = sWn[k * 32 + lane];
                acc.x = fmaf(pb[i], w1.x, acc.x);
                acc.y = fmaf(pb[i], w1.y, acc.y);
                acc.z = fmaf(pb[i], w1.z, acc.z);
                acc.w = fmaf(pb[i], w1.w, acc.w);
                float4 w2 = sWs[k * 32 + lane];
                acc.x = fmaf(hb[i], w2.x, acc.x);
                acc.y = fmaf(hb[i], w2.y, acc.y);
                acc.z = fmaf(hb[i], w2.z, acc.z);
                acc.w = fmaf(hb[i], w2.w, acc.w);
            }
        }

        // rrelu (eval mode = leaky with mean slope)
        acc.x = acc.x >= 0.f ? acc.x : SL * acc.x;
        acc.y = acc.y >= 0.f ? acc.y : SL * acc.y;
        acc.z = acc.z >= 0.f ? acc.z : SL * acc.z;
        acc.w = acc.w >= 0.f ? acc.w : SL * acc.w;

        // gate GEMV
        float4 g = bb;
#pragma unroll 4
        for (int kq = 0; kq < 32; kq++) {
            float ab[4];
            ab[0] = __shfl_sync(0xffffffffu, acc.x, kq);
            ab[1] = __shfl_sync(0xffffffffu, acc.y, kq);
            ab[2] = __shfl_sync(0xffffffffu, acc.z, kq);
            ab[3] = __shfl_sync(0xffffffffu, acc.w, kq);
#pragma unroll
            for (int i = 0; i < 4; i++) {
                int k = kq * 4 + i;
                float4 w = sWg[k * 32 + lane];
                g.x = fmaf(ab[i], w.x, g.x);
                g.y = fmaf(ab[i], w.y, g.y);
                g.z = fmaf(ab[i], w.z, g.z);
                g.w = fmaf(ab[i], w.w, g.w);
            }
        }
        g.x = 1.0f / (1.0f + expf(-g.x));
        g.y = 1.0f / (1.0f + expf(-g.y));
        g.z = 1.0f / (1.0f + expf(-g.z));
        g.w = 1.0f / (1.0f + expf(-g.w));

        float4 hs = his[n * 32 + lane];
        float4 o;
        o.x = fmaf(g.x, acc.x - hs.x, hs.x);
        o.y = fmaf(g.y, acc.y - hs.y, hs.y);
        o.z = fmaf(g.z, acc.z - hs.z, hs.z);
        o.w = fmaf(g.w, acc.w - hs.w, hs.w);
        out[n * 32 + lane] = o;
    }
}

// ---------------------------------------------------------------------------
// Launch
// ---------------------------------------------------------------------------
extern "C" void kernel_launch(void* const* d_in, const int* in_sizes, int n_in,
                              void* d_out, int out_size) {
    const float4* ent  = (const float4*)d_in[0];
    const float4* rel  = (const float4*)d_in[1];
    const float4* his  = (const float4*)d_in[2];
    const float4* Wn   = (const float4*)d_in[3];
    const float4* Ws   = (const float4*)d_in[4];
    const float4* Wg   = (const float4*)d_in[5];
    const float4* bias = (const float4*)d_in[6];
    const float*  enorm = (const float*)d_in[7];
    const int*    src  = (const int*)d_in[8];
    const int*    dst  = (const int*)d_in[9];
    const int*    et   = (const int*)d_in[10];
    float4* out = (float4*)d_out;

    // Kernel 1: normalize + zero scratch. Warp per node.
    {
        long long threads = (long long)NENT * 32;
        int blocks = (int)((threads + 255) / 256);
        k_norm<<<blocks, 256>>>(ent);
    }
    // Kernel 2: edge scatter. Warp per edge.
    {
        long long threads = (long long)NEDGE * 32;
        int blocks = (int)((threads + 255) / 256);
        k_edge<<<blocks, 256>>>(rel, enorm, src, dst, et);
    }
    // Kernel 3: fused node epilogue (192 KB smem).
    {
        int smem = 3 * 4096 * (int)sizeof(float4);
        cudaFuncSetAttribute(k_node, cudaFuncAttributeMaxDynamicSharedMemorySize, smem);
        k_node<<<152, 512, smem>>>(his, bias, Wn, Ws, Wg, out);
    }
}

// round 3
// speedup vs baseline: 2.1812x; 2.1812x over previous
#include <cuda_runtime.h>
#include <cstdint>

#define NENT 100000
#define NEDGE 2000000
#define PITCH 136  // smem row pitch in 32-bit words: 128+8 -> conflict-free B frags

// Scratch buffers
__device__ float4 g_h[NENT * 32];     // normalized embeddings
__device__ float4 g_pre[NENT * 32];   // edge aggregation
__device__ float4 g_hcur[NENT * 32];  // post-rrelu hidden state

// ---------------------------------------------------------------------------
// Kernel 1: L2-normalize ent_emb -> g_h, zero g_pre. Warp per node.
// ---------------------------------------------------------------------------
__global__ void k_norm(const float4* __restrict__ ent) {
    int gw = (blockIdx.x * blockDim.x + threadIdx.x) >> 5;
    int lane = threadIdx.x & 31;
    if (gw >= NENT) return;
    float4 v = ent[gw * 32 + lane];
    float s = v.x * v.x + v.y * v.y + v.z * v.z + v.w * v.w;
#pragma unroll
    for (int o = 16; o; o >>= 1) s += __shfl_xor_sync(0xffffffffu, s, o);
    float inv = 1.0f / fmaxf(sqrtf(s), 1e-12f);
    v.x *= inv; v.y *= inv; v.z *= inv; v.w *= inv;
    g_h[gw * 32 + lane] = v;
    g_pre[gw * 32 + lane] = make_float4(0.f, 0.f, 0.f, 0.f);
}

// ---------------------------------------------------------------------------
// Kernel 2: per-edge scatter: pre[dst] += norm * (h[src] + rel[etype]).
// Warp per edge; red.global.add.v4.f32.
// ---------------------------------------------------------------------------
__global__ void k_edge(const float4* __restrict__ rel,
                       const float* __restrict__ enorm,
                       const int* __restrict__ src,
                       const int* __restrict__ dst,
                       const int* __restrict__ et) {
    int e = (blockIdx.x * blockDim.x + threadIdx.x) >> 5;
    int lane = threadIdx.x & 31;
    if (e >= NEDGE) return;
    int s = src[e];
    int d = dst[e];
    int t = et[e];
    float w = enorm[e];
    float4 hv = g_h[s * 32 + lane];
    float4 rv = rel[t * 32 + lane];
    float4 m;
    m.x = (hv.x + rv.x) * w;
    m.y = (hv.y + rv.y) * w;
    m.z = (hv.z + rv.z) * w;
    m.w = (hv.w + rv.w) * w;
    float* p = (float*)(g_pre + (size_t)d * 32 + lane);
    asm volatile("red.global.add.v4.f32 [%0], {%1,%2,%3,%4};"
                 :: "l"(p), "f"(m.x), "f"(m.y), "f"(m.z), "f"(m.w)
                 : "memory");
}

// ---------------------------------------------------------------------------
// tf32 helpers
// ---------------------------------------------------------------------------
__device__ __forceinline__ unsigned f2tf(float x) {
    unsigned r;
    asm("cvt.rna.tf32.f32 %0, %1;" : "=r"(r) : "f"(x));
    return r;
}

__device__ __forceinline__ void mma_tf32(float c[4], unsigned a0, unsigned a1,
                                         unsigned a2, unsigned a3,
                                         unsigned b0, unsigned b1) {
    asm volatile(
        "mma.sync.aligned.m16n8k8.row.col.f32.tf32.tf32.f32 "
        "{%0,%1,%2,%3}, {%4,%5,%6,%7}, {%8,%9}, {%0,%1,%2,%3};"
        : "+f"(c[0]), "+f"(c[1]), "+f"(c[2]), "+f"(c[3])
        : "r"(a0), "r"(a1), "r"(a2), "r"(a3), "r"(b0), "r"(b1));
}

// ---------------------------------------------------------------------------
// Kernel 3: GEMM1  h_cur = rrelu( [pre|h] @ [Wn;Ws] )   (tf32 mma.sync)
// Warp computes 16 nodes x 128 outputs. Weights (tf32) in smem, pitch 136.
// ---------------------------------------------------------------------------
__global__ void __launch_bounds__(512, 1)
k_gemm1(const float* __restrict__ Wn, const float* __restrict__ Ws) {
    extern __shared__ unsigned sW[];  // 256 x PITCH tf32 words
    for (int i = threadIdx.x; i < 256 * 128; i += blockDim.x) {
        int r = i >> 7, c = i & 127;
        float v = (r < 128) ? Wn[r * 128 + c] : Ws[(r - 128) * 128 + c];
        sW[r * PITCH + c] = f2tf(v);
    }
    __syncthreads();

    const int lane = threadIdx.x & 31;
    const int warp = threadIdx.x >> 5;
    const int g = lane >> 2, tig = lane & 3;
    const float* pre = (const float*)g_pre;
    const float* hh = (const float*)g_h;
    const float SL = 0.22916666666666666f;

    for (int tile = blockIdx.x * 16 + warp; tile < NENT / 16; tile += gridDim.x * 16) {
        int n0 = tile * 16;
        float acc[16][4];
#pragma unroll
        for (int nt = 0; nt < 16; nt++) {
            acc[nt][0] = 0.f; acc[nt][1] = 0.f; acc[nt][2] = 0.f; acc[nt][3] = 0.f;
        }

        for (int kk = 0; kk < 32; kk++) {
            const float* base = (kk < 16) ? pre : hh;
            int kr = (kk & 15) * 8;
            const float* r0 = base + (size_t)(n0 + g) * 128 + kr;
            const float* r1 = base + (size_t)(n0 + 8 + g) * 128 + kr;
            unsigned a0 = f2tf(r0[tig]);
            unsigned a1 = f2tf(r1[tig]);
            unsigned a2 = f2tf(r0[tig + 4]);
            unsigned a3 = f2tf(r1[tig + 4]);
            const unsigned* bp = sW + (kk * 8 + tig) * PITCH + g;
#pragma unroll
            for (int nt = 0; nt < 16; nt++) {
                unsigned b0 = bp[nt * 8];
                unsigned b1 = bp[4 * PITCH + nt * 8];
                mma_tf32(acc[nt], a0, a1, a2, a3, b0, b1);
            }
        }

        float2* out = (float2*)g_hcur;
#pragma unroll
        for (int nt = 0; nt < 16; nt++) {
            float v0 = acc[nt][0], v1 = acc[nt][1], v2 = acc[nt][2], v3 = acc[nt][3];
            v0 = v0 >= 0.f ? v0 : SL * v0;
            v1 = v1 >= 0.f ? v1 : SL * v1;
            v2 = v2 >= 0.f ? v2 : SL * v2;
            v3 = v3 >= 0.f ? v3 : SL * v3;
            out[(size_t)(n0 + g) * 64 + nt * 4 + tig] = make_float2(v0, v1);
            out[(size_t)(n0 + 8 + g) * 64 + nt * 4 + tig] = make_float2(v2, v3);
        }
    }
}

// ---------------------------------------------------------------------------
// Kernel 4: GEMM2 + gate:  gate = sigmoid(h_cur @ Wg + b);
//           out = gate*h_cur + (1-gate)*his
// ---------------------------------------------------------------------------
__global__ void __launch_bounds__(512, 1)
k_gemm2(const float* __restrict__ Wg, const float* __restrict__ bias,
        const float* __restrict__ his, float* __restrict__ outp) {
    extern __shared__ unsigned sW[];  // 128 x PITCH tf32 words
    for (int i = threadIdx.x; i < 128 * 128; i += blockDim.x) {
        int r = i >> 7, c = i & 127;
        sW[r * PITCH + c] = f2tf(Wg[r * 128 + c]);
    }
    __syncthreads();

    const int lane = threadIdx.x & 31;
    const int warp = threadIdx.x >> 5;
    const int g = lane >> 2, tig = lane & 3;
    const float* hcur = (const float*)g_hcur;

    // bias per (nt): cols nt*8 + 2*tig, +1
    float2 bs[16];
#pragma unroll
    for (int nt = 0; nt < 16; nt++)
        bs[nt] = ((const float2*)bias)[nt * 4 + tig];

    for (int tile = blockIdx.x * 16 + warp; tile < NENT / 16; tile += gridDim.x * 16) {
        int n0 = tile * 16;
        float acc[16][4];
#pragma unroll
        for (int nt = 0; nt < 16; nt++) {
            acc[nt][0] = 0.f; acc[nt][1] = 0.f; acc[nt][2] = 0.f; acc[nt][3] = 0.f;
        }

        for (int kk = 0; kk < 16; kk++) {
            int kr = kk * 8;
            const float* r0 = hcur + (size_t)(n0 + g) * 128 + kr;
            const float* r1 = hcur + (size_t)(n0 + 8 + g) * 128 + kr;
            unsigned a0 = f2tf(r0[tig]);
            unsigned a1 = f2tf(r1[tig]);
            unsigned a2 = f2tf(r0[tig + 4]);
            unsigned a3 = f2tf(r1[tig + 4]);
            const unsigned* bp = sW + (kr + tig) * PITCH + g;
#pragma unroll
            for (int nt = 0; nt < 16; nt++) {
                unsigned b0 = bp[nt * 8];
                unsigned b1 = bp[4 * PITCH + nt * 8];
                mma_tf32(acc[nt], a0, a1, a2, a3, b0, b1);
            }
        }

        const float2* hc2 = (const float2*)g_hcur;
        const float2* hs2 = (const float2*)his;
        float2* o2 = (float2*)outp;
#pragma unroll
        for (int nt = 0; nt < 16; nt++) {
            // row g (acc[nt][0], acc[nt][1])
            {
                size_t idx = (size_t)(n0 + g) * 64 + nt * 4 + tig;
                float2 hc = hc2[idx];
                float2 hs = hs2[idx];
                float gx = 1.0f / (1.0f + expf(-(acc[nt][0] + bs[nt].x)));
                float gy = 1.0f / (1.0f + expf(-(acc[nt][1] + bs[nt].y)));
                float2 o;
                o.x = fmaf(gx, hc.x - hs.x, hs.x);
                o.y = fmaf(gy, hc.y - hs.y, hs.y);
                o2[idx] = o;
            }
            // row g+8 (acc[nt][2], acc[nt][3])
            {
                size_t idx = (size_t)(n0 + 8 + g) * 64 + nt * 4 + tig;
                float2 hc = hc2[idx];
                float2 hs = hs2[idx];
                float gx = 1.0f / (1.0f + expf(-(acc[nt][2] + bs[nt].x)));
                float gy = 1.0f / (1.0f + expf(-(acc[nt][3] + bs[nt].y)));
                float2 o;
                o.x = fmaf(gx, hc.x - hs.x, hs.x);
                o.y = fmaf(gy, hc.y - hs.y, hs.y);
                o2[idx] = o;
            }
        }
    }
}

// ---------------------------------------------------------------------------
// Launch
// ---------------------------------------------------------------------------
extern "C" void kernel_launch(void* const* d_in, const int* in_sizes, int n_in,
                              void* d_out, int out_size) {
    const float4* ent  = (const float4*)d_in[0];
    const float4* rel  = (const float4*)d_in[1];
    const float*  his  = (const float*)d_in[2];
    const float*  Wn   = (const float*)d_in[3];
    const float*  Ws   = (const float*)d_in[4];
    const float*  Wg   = (const float*)d_in[5];
    const float*  bias = (const float*)d_in[6];
    const float*  enorm = (const float*)d_in[7];
    const int*    src  = (const int*)d_in[8];
    const int*    dst  = (const int*)d_in[9];
    const int*    et   = (const int*)d_in[10];
    float* out = (float*)d_out;

    // Kernel 1: normalize + zero scratch
    {
        long long threads = (long long)NENT * 32;
        int blocks = (int)((threads + 255) / 256);
        k_norm<<<blocks, 256>>>(ent);
    }
    // Kernel 2: edge scatter
    {
        long long threads = (long long)NEDGE * 32;
        int blocks = (int)((threads + 255) / 256);
        k_edge<<<blocks, 256>>>(rel, enorm, src, dst, et);
    }
    // Kernel 3: GEMM1 (tf32), 139 KB smem
    {
        int smem = 256 * PITCH * 4;
        cudaFuncSetAttribute(k_gemm1, cudaFuncAttributeMaxDynamicSharedMemorySize, smem);
        k_gemm1<<<148, 512, smem>>>(Wn, Ws);
    }
    // Kernel 4: GEMM2 + gate (tf32), 70 KB smem
    {
        int smem = 128 * PITCH * 4;
        cudaFuncSetAttribute(k_gemm2, cudaFuncAttributeMaxDynamicSharedMemorySize, smem);
        k_gemm2<<<148, 512, smem>>>(Wg, bias, his, out);
    }
}

// round 4
// speedup vs baseline: 2.3586x; 1.0813x over previous
#include <cuda_runtime.h>
#include <cstdint>

#define NENT 100000
#define NEDGE 2000000
#define NTILE 6250          // NENT / 16
#define PITCH 136           // weight smem pitch (words): conflict-free B frags
#define SCAN_B 196          // ceil(NENT / 512)

// ---------------------------------------------------------------------------
// Scratch
// ---------------------------------------------------------------------------
__device__ float4   g_h[NENT * 32];         // normalized embeddings, row-major (for gather)
__device__ unsigned g_h_frag[NENT * 128];   // same, tf32 in mma-A-fragment layout
__device__ unsigned g_pre_frag[NENT * 128]; // edge aggregation, tf32 A-frag layout
__device__ float4   g_hcur[NENT * 32];      // post-rrelu hidden, row-major (for epilogue)
__device__ unsigned g_hcur_frag[NENT * 128];// same, tf32 A-frag layout
__device__ float4   g_pay[NEDGE];           // sorted edge payload {src, etype, norm, -}
__device__ int g_cnt[NENT];
__device__ int g_off[NENT];
__device__ int g_cur[NENT];
__device__ int g_part[SCAN_B];

__device__ __forceinline__ unsigned f2tf(float x) {
    unsigned r;
    asm("cvt.rna.tf32.f32 %0, %1;" : "=r"(r) : "f"(x));
    return r;
}

// A-fragment layout: tile t (16 rows), kstep kk (8 cols). Word address:
//   ((t*16 + kk)*32 + lane)*4 + j
// where for (row-in-tile lr, col c): kk=c>>3, lane=(lr&7)*4 + (c&3),
//   j = (lr>>3) + 2*((c>>2)&1)
__device__ __forceinline__ void frag_store(unsigned* buf, int n, int c, float v) {
    int t = n >> 4, lr = n & 15;
    int kk = c >> 3;
    int lane = ((lr & 7) << 2) | (c & 3);
    int j = (lr >> 3) | (((c >> 2) & 1) << 1);
    buf[(((t << 4) + kk) << 7) + (lane << 2) + j] = f2tf(v);
}

// ---------------------------------------------------------------------------
// Kernel 1: L2-normalize -> g_h (row-major) + g_h_frag (tf32 frags); zero cnt.
// Warp per node.
// ---------------------------------------------------------------------------
__global__ void k_norm(const float4* __restrict__ ent) {
    int gw = (blockIdx.x * blockDim.x + threadIdx.x) >> 5;
    int lane = threadIdx.x & 31;
    if (gw >= NENT) return;
    float4 v = ent[gw * 32 + lane];
    float s = v.x * v.x + v.y * v.y + v.z * v.z + v.w * v.w;
#pragma unroll
    for (int o = 16; o; o >>= 1) s += __shfl_xor_sync(0xffffffffu, s, o);
    float inv = 1.0f / fmaxf(sqrtf(s), 1e-12f);
    v.x *= inv; v.y *= inv; v.z *= inv; v.w *= inv;
    g_h[gw * 32 + lane] = v;
    int c0 = lane * 4;
    frag_store(g_h_frag, gw, c0 + 0, v.x);
    frag_store(g_h_frag, gw, c0 + 1, v.y);
    frag_store(g_h_frag, gw, c0 + 2, v.z);
    frag_store(g_h_frag, gw, c0 + 3, v.w);
    if (lane == 0) g_cnt[gw] = 0;
}

// ---------------------------------------------------------------------------
// CSR build: histogram, 3-phase exclusive scan, ticketed scatter.
// ---------------------------------------------------------------------------
__global__ void k_hist(const int* __restrict__ dst) {
    int e = blockIdx.x * blockDim.x + threadIdx.x;
    if (e < NEDGE) atomicAdd(&g_cnt[dst[e]], 1);
}

__global__ void k_scan_part() {
    int i = blockIdx.x * 512 + threadIdx.x;
    int v = (i < NENT) ? g_cnt[i] : 0;
    int lane = threadIdx.x & 31, wid = threadIdx.x >> 5;
#pragma unroll
    for (int o = 16; o; o >>= 1) v += __shfl_xor_sync(0xffffffffu, v, o);
    __shared__ int ws[16];
    if (lane == 0) ws[wid] = v;
    __syncthreads();
    if (threadIdx.x < 16) {
        int x = ws[threadIdx.x];
#pragma unroll
        for (int o = 8; o; o >>= 1) x += __shfl_xor_sync(0xffffu, x, o);
        if (threadIdx.x == 0) g_part[blockIdx.x] = x;
    }
}

__global__ void k_scan_top() {
    __shared__ int s[256];
    int t = threadIdx.x;
    int v = (t < SCAN_B) ? g_part[t] : 0;
    s[t] = v;
    __syncthreads();
    for (int d = 1; d < 256; d <<= 1) {
        int x = (t >= d) ? s[t - d] : 0;
        __syncthreads();
        s[t] += x;
        __syncthreads();
    }
    if (t < SCAN_B) g_part[t] = s[t] - v;  // exclusive
}

__global__ void k_scan_final() {
    __shared__ int s[512];
    int i = blockIdx.x * 512 + threadIdx.x;
    int t = threadIdx.x;
    int v = (i < NENT) ? g_cnt[i] : 0;
    s[t] = v;
    __syncthreads();
    for (int d = 1; d < 512; d <<= 1) {
        int x = (t >= d) ? s[t - d] : 0;
        __syncthreads();
        s[t] += x;
        __syncthreads();
    }
    if (i < NENT) {
        int off = g_part[blockIdx.x] + s[t] - v;
        g_off[i] = off;
        g_cur[i] = off;
    }
}

__global__ void k_scatter(const float* __restrict__ enorm,
                          const int* __restrict__ src,
                          const int* __restrict__ dst,
                          const int* __restrict__ et) {
    int e = blockIdx.x * blockDim.x + threadIdx.x;
    if (e >= NEDGE) return;
    int d = dst[e];
    int pos = atomicAdd(&g_cur[d], 1);
    g_pay[pos] = make_float4(__int_as_float(src[e]), __int_as_float(et[e]),
                             enorm[e], 0.f);
}

// ---------------------------------------------------------------------------
// Aggregation: warp per dst. acc = sum_e norm * (h[src] + rel[et]).
// Writes g_pre_frag (tf32 A-fragment layout).
// ---------------------------------------------------------------------------
__global__ void k_agg(const float4* __restrict__ rel) {
    int gw = (blockIdx.x * blockDim.x + threadIdx.x) >> 5;
    int lane = threadIdx.x & 31;
    if (gw >= NENT) return;
    int cnt = g_cnt[gw];
    int off = g_off[gw];
    float4 acc = make_float4(0.f, 0.f, 0.f, 0.f);
    int i = 0;
    for (; i + 2 <= cnt; i += 2) {
        float4 p0 = g_pay[off + i];
        float4 p1 = g_pay[off + i + 1];
        int s0 = __float_as_int(p0.x), t0 = __float_as_int(p0.y);
        int s1 = __float_as_int(p1.x), t1 = __float_as_int(p1.y);
        float4 h0 = g_h[(size_t)s0 * 32 + lane];
        float4 r0 = rel[(size_t)t0 * 32 + lane];
        float4 h1 = g_h[(size_t)s1 * 32 + lane];
        float4 r1 = rel[(size_t)t1 * 32 + lane];
        acc.x += (h0.x + r0.x) * p0.z + (h1.x + r1.x) * p1.z;
        acc.y += (h0.y + r0.y) * p0.z + (h1.y + r1.y) * p1.z;
        acc.z += (h0.z + r0.z) * p0.z + (h1.z + r1.z) * p1.z;
        acc.w += (h0.w + r0.w) * p0.z + (h1.w + r1.w) * p1.z;
    }
    if (i < cnt) {
        float4 p0 = g_pay[off + i];
        int s0 = __float_as_int(p0.x), t0 = __float_as_int(p0.y);
        float4 h0 = g_h[(size_t)s0 * 32 + lane];
        float4 r0 = rel[(size_t)t0 * 32 + lane];
        acc.x += (h0.x + r0.x) * p0.z;
        acc.y += (h0.y + r0.y) * p0.z;
        acc.z += (h0.z + r0.z) * p0.z;
        acc.w += (h0.w + r0.w) * p0.z;
    }
    int c0 = lane * 4;
    frag_store(g_pre_frag, gw, c0 + 0, acc.x);
    frag_store(g_pre_frag, gw, c0 + 1, acc.y);
    frag_store(g_pre_frag, gw, c0 + 2, acc.z);
    frag_store(g_pre_frag, gw, c0 + 3, acc.w);
}

// ---------------------------------------------------------------------------
// tf32 mma
// ---------------------------------------------------------------------------
__device__ __forceinline__ void mma_tf32(float c[4], unsigned a0, unsigned a1,
                                         unsigned a2, unsigned a3,
                                         unsigned b0, unsigned b1) {
    asm volatile(
        "mma.sync.aligned.m16n8k8.row.col.f32.tf32.tf32.f32 "
        "{%0,%1,%2,%3}, {%4,%5,%6,%7}, {%8,%9}, {%0,%1,%2,%3};"
        : "+f"(c[0]), "+f"(c[1]), "+f"(c[2]), "+f"(c[3])
        : "r"(a0), "r"(a1), "r"(a2), "r"(a3), "r"(b0), "r"(b1));
}

// ---------------------------------------------------------------------------
// GEMM1: h_cur = rrelu( [pre|h] @ [Wn;Ws] ). A from fragment buffers (uint4).
// Writes g_hcur row-major + g_hcur_frag.
// ---------------------------------------------------------------------------
__global__ void __launch_bounds__(512, 1)
k_gemm1(const float* __restrict__ Wn, const float* __restrict__ Ws) {
    extern __shared__ unsigned sW[];  // 256 x PITCH
    for (int i = threadIdx.x; i < 256 * 128; i += blockDim.x) {
        int r = i >> 7, c = i & 127;
        float v = (r < 128) ? Wn[r * 128 + c] : Ws[(r - 128) * 128 + c];
        sW[r * PITCH + c] = f2tf(v);
    }
    __syncthreads();

    const int lane = threadIdx.x & 31;
    const int warp = threadIdx.x >> 5;
    const int g = lane >> 2, tig = lane & 3;
    const float SL = 0.22916666666666666f;
    const uint4* preF = (const uint4*)g_pre_frag;
    const uint4* hF = (const uint4*)g_h_frag;

    for (int tile = blockIdx.x * 16 + warp; tile < NTILE; tile += gridDim.x * 16) {
        int n0 = tile * 16;
        float acc[16][4];
#pragma unroll
        for (int nt = 0; nt < 16; nt++) {
            acc[nt][0] = 0.f; acc[nt][1] = 0.f; acc[nt][2] = 0.f; acc[nt][3] = 0.f;
        }

        for (int kk = 0; kk < 32; kk++) {
            int ks = kk & 15;
            const uint4* buf = (kk < 16) ? preF : hF;
            uint4 af = buf[(size_t)(tile * 16 + ks) * 32 + lane];
            const unsigned* bp = sW + (kk * 8 + tig) * PITCH + g;
#pragma unroll
            for (int nt = 0; nt < 16; nt++) {
                unsigned b0 = bp[nt * 8];
                unsigned b1 = bp[4 * PITCH + nt * 8];
                mma_tf32(acc[nt], af.x, af.y, af.z, af.w, b0, b1);
            }
        }

        float2* out = (float2*)g_hcur;
#pragma unroll
        for (int nt = 0; nt < 16; nt++) {
            float v0 = acc[nt][0], v1 = acc[nt][1], v2 = acc[nt][2], v3 = acc[nt][3];
            v0 = v0 >= 0.f ? v0 : SL * v0;
            v1 = v1 >= 0.f ? v1 : SL * v1;
            v2 = v2 >= 0.f ? v2 : SL * v2;
            v3 = v3 >= 0.f ? v3 : SL * v3;
            out[(size_t)(n0 + g) * 64 + nt * 4 + tig] = make_float2(v0, v1);
            out[(size_t)(n0 + 8 + g) * 64 + nt * 4 + tig] = make_float2(v2, v3);
            int cb = nt * 8 + 2 * tig;
            frag_store(g_hcur_frag, n0 + g,     cb,     v0);
            frag_store(g_hcur_frag, n0 + g,     cb + 1, v1);
            frag_store(g_hcur_frag, n0 + 8 + g, cb,     v2);
            frag_store(g_hcur_frag, n0 + 8 + g, cb + 1, v3);
        }
    }
}

// ---------------------------------------------------------------------------
// GEMM2 + gate: gate = sigmoid(h_cur @ Wg + b); out = gate*h_cur + (1-gate)*his
// ---------------------------------------------------------------------------
__global__ void __launch_bounds__(512, 1)
k_gemm2(const float* __restrict__ Wg, const float* __restrict__ bias,
        const float* __restrict__ his, float* __restrict__ outp) {
    extern __shared__ unsigned sW[];  // 128 x PITCH
    for (int i = threadIdx.x; i < 128 * 128; i += blockDim.x) {
        int r = i >> 7, c = i & 127;
        sW[r * PITCH + c] = f2tf(Wg[r * 128 + c]);
    }
    __syncthreads();

    const int lane = threadIdx.x & 31;
    const int warp = threadIdx.x >> 5;
    const int g = lane >> 2, tig = lane & 3;
    const uint4* hcF = (const uint4*)g_hcur_frag;

    float2 bs[16];
#pragma unroll
    for (int nt = 0; nt < 16; nt++)
        bs[nt] = ((const float2*)bias)[nt * 4 + tig];

    for (int tile = blockIdx.x * 16 + warp; tile < NTILE; tile += gridDim.x * 16) {
        int n0 = tile * 16;
        float acc[16][4];
#pragma unroll
        for (int nt = 0; nt < 16; nt++) {
            acc[nt][0] = 0.f; acc[nt][1] = 0.f; acc[nt][2] = 0.f; acc[nt][3] = 0.f;
        }

        for (int kk = 0; kk < 16; kk++) {
            uint4 af = hcF[(size_t)(tile * 16 + kk) * 32 + lane];
            const unsigned* bp = sW + (kk * 8 + tig) * PITCH + g;
#pragma unroll
            for (int nt = 0; nt < 16; nt++) {
                unsigned b0 = bp[nt * 8];
                unsigned b1 = bp[4 * PITCH + nt * 8];
                mma_tf32(acc[nt], af.x, af.y, af.z, af.w, b0, b1);
            }
        }

        const float2* hc2 = (const float2*)g_hcur;
        const float2* hs2 = (const float2*)his;
        float2* o2 = (float2*)outp;
#pragma unroll
        for (int nt = 0; nt < 16; nt++) {
            {
                size_t idx = (size_t)(n0 + g) * 64 + nt * 4 + tig;
                float2 hc = hc2[idx];
                float2 hs = hs2[idx];
                float gx = 1.0f / (1.0f + expf(-(acc[nt][0] + bs[nt].x)));
                float gy = 1.0f / (1.0f + expf(-(acc[nt][1] + bs[nt].y)));
                float2 o;
                o.x = fmaf(gx, hc.x - hs.x, hs.x);
                o.y = fmaf(gy, hc.y - hs.y, hs.y);
                o2[idx] = o;
            }
            {
                size_t idx = (size_t)(n0 + 8 + g) * 64 + nt * 4 + tig;
                float2 hc = hc2[idx];
                float2 hs = hs2[idx];
                float gx = 1.0f / (1.0f + expf(-(acc[nt][2] + bs[nt].x)));
                float gy = 1.0f / (1.0f + expf(-(acc[nt][3] + bs[nt].y)));
                float2 o;
                o.x = fmaf(gx, hc.x - hs.x, hs.x);
                o.y = fmaf(gy, hc.y - hs.y, hs.y);
                o2[idx] = o;
            }
        }
    }
}

// ---------------------------------------------------------------------------
// Launch
// ---------------------------------------------------------------------------
extern "C" void kernel_launch(void* const* d_in, const int* in_sizes, int n_in,
                              void* d_out, int out_size) {
    const float4* ent  = (const float4*)d_in[0];
    const float4* rel  = (const float4*)d_in[1];
    const float*  his  = (const float*)d_in[2];
    const float*  Wn   = (const float*)d_in[3];
    const float*  Ws   = (const float*)d_in[4];
    const float*  Wg   = (const float*)d_in[5];
    const float*  bias = (const float*)d_in[6];
    const float*  enorm = (const float*)d_in[7];
    const int*    src  = (const int*)d_in[8];
    const int*    dst  = (const int*)d_in[9];
    const int*    et   = (const int*)d_in[10];
    float* out = (float*)d_out;

    k_norm<<<(NENT * 32 + 255) / 256, 256>>>(ent);
    k_hist<<<(NEDGE + 511) / 512, 512>>>(dst);
    k_scan_part<<<SCAN_B, 512>>>();
    k_scan_top<<<1, 256>>>();
    k_scan_final<<<SCAN_B, 512>>>();
    k_scatter<<<(NEDGE + 511) / 512, 512>>>(enorm, src, dst, et);
    k_agg<<<(NENT * 32 + 511) / 512, 512>>>(rel);
    {
        int smem = 256 * PITCH * 4;
        cudaFuncSetAttribute(k_gemm1, cudaFuncAttributeMaxDynamicSharedMemorySize, smem);
        k_gemm1<<<148, 512, smem>>>(Wn, Ws);
    }
    {
        int smem = 128 * PITCH * 4;
        cudaFuncSetAttribute(k_gemm2, cudaFuncAttributeMaxDynamicSharedMemorySize, smem);
        k_gemm2<<<148, 512, smem>>>(Wg, bias, his, out);
    }
}

// round 5
// speedup vs baseline: 2.6810x; 1.1367x over previous
#include <cuda_runtime.h>
#include <cuda_fp16.h>
#include <cstdint>

#define NENT 100000
#define NEDGE 2000000
#define NREL 1000
#define NTILE 6250          // NENT / 16
#define PITCH 136           // weight smem pitch (words): conflict-free B frags
#define SCAN_B 196          // ceil(NENT / 512)

// ---------------------------------------------------------------------------
// Scratch
// ---------------------------------------------------------------------------
__device__ uint2    g_hh[NENT * 32];        // normalized embeddings, fp16x4 per lane-slot
__device__ uint2    g_relh[NREL * 32];      // rel embeddings, fp16
__device__ unsigned g_h_frag[NENT * 128];   // normalized emb, tf32 mma-A-fragment layout
__device__ unsigned g_pre_frag[NENT * 128]; // edge aggregation, tf32 A-frag layout
__device__ float4   g_hcur[NENT * 32];      // post-rrelu hidden, row-major
__device__ unsigned g_hcur_frag[NENT * 128];// same, tf32 A-frag layout
__device__ float4   g_pay[NEDGE];           // sorted edge payload {src, etype, norm, -}
__device__ int g_cnt[NENT];
__device__ int g_off[NENT];
__device__ int g_cur[NENT];
__device__ int g_part[SCAN_B];

__device__ __forceinline__ unsigned f2tf(float x) {
    unsigned r;
    asm("cvt.rna.tf32.f32 %0, %1;" : "=r"(r) : "f"(x));
    return r;
}

// A-fragment layout: tile t (16 rows), kstep kk (8 cols). Word address:
//   ((t*16 + kk)*32 + lane)*4 + j
__device__ __forceinline__ void frag_store(unsigned* buf, int n, int c, float v) {
    int t = n >> 4, lr = n & 15;
    int kk = c >> 3;
    int lane = ((lr & 7) << 2) | (c & 3);
    int j = (lr >> 3) | (((c >> 2) & 1) << 1);
    buf[(((t << 4) + kk) << 7) + (lane << 2) + j] = f2tf(v);
}

__device__ __forceinline__ uint2 pack_h4(float a, float b, float c, float d) {
    __half2 lo = __floats2half2_rn(a, b);
    __half2 hi = __floats2half2_rn(c, d);
    uint2 r;
    r.x = *(unsigned*)&lo;
    r.y = *(unsigned*)&hi;
    return r;
}

// ---------------------------------------------------------------------------
// Kernel 1: L2-normalize -> g_hh (fp16) + g_h_frag (tf32 frags); zero cnt.
// ---------------------------------------------------------------------------
__global__ void k_norm(const float4* __restrict__ ent) {
    int gw = (blockIdx.x * blockDim.x + threadIdx.x) >> 5;
    int lane = threadIdx.x & 31;
    if (gw >= NENT) return;
    float4 v = ent[gw * 32 + lane];
    float s = v.x * v.x + v.y * v.y + v.z * v.z + v.w * v.w;
#pragma unroll
    for (int o = 16; o; o >>= 1) s += __shfl_xor_sync(0xffffffffu, s, o);
    float inv = 1.0f / fmaxf(sqrtf(s), 1e-12f);
    v.x *= inv; v.y *= inv; v.z *= inv; v.w *= inv;
    g_hh[gw * 32 + lane] = pack_h4(v.x, v.y, v.z, v.w);
    int c0 = lane * 4;
    frag_store(g_h_frag, gw, c0 + 0, v.x);
    frag_store(g_h_frag, gw, c0 + 1, v.y);
    frag_store(g_h_frag, gw, c0 + 2, v.z);
    frag_store(g_h_frag, gw, c0 + 3, v.w);
    if (lane == 0) g_cnt[gw] = 0;
}

// rel -> fp16 copy (tiny)
__global__ void k_relh(const float4* __restrict__ rel) {
    int gw = (blockIdx.x * blockDim.x + threadIdx.x) >> 5;
    int lane = threadIdx.x & 31;
    if (gw >= NREL) return;
    float4 v = rel[gw * 32 + lane];
    g_relh[gw * 32 + lane] = pack_h4(v.x, v.y, v.z, v.w);
}

// ---------------------------------------------------------------------------
// CSR build: histogram, 3-phase exclusive scan, ticketed scatter.
// ---------------------------------------------------------------------------
__global__ void k_hist(const int* __restrict__ dst) {
    int e = blockIdx.x * blockDim.x + threadIdx.x;
    if (e < NEDGE) atomicAdd(&g_cnt[dst[e]], 1);
}

__global__ void k_scan_part() {
    int i = blockIdx.x * 512 + threadIdx.x;
    int v = (i < NENT) ? g_cnt[i] : 0;
    int lane = threadIdx.x & 31, wid = threadIdx.x >> 5;
#pragma unroll
    for (int o = 16; o; o >>= 1) v += __shfl_xor_sync(0xffffffffu, v, o);
    __shared__ int ws[16];
    if (lane == 0) ws[wid] = v;
    __syncthreads();
    if (threadIdx.x < 16) {
        int x = ws[threadIdx.x];
#pragma unroll
        for (int o = 8; o; o >>= 1) x += __shfl_xor_sync(0xffffu, x, o);
        if (threadIdx.x == 0) g_part[blockIdx.x] = x;
    }
}

__global__ void k_scan_top() {
    __shared__ int s[256];
    int t = threadIdx.x;
    int v = (t < SCAN_B) ? g_part[t] : 0;
    s[t] = v;
    __syncthreads();
    for (int d = 1; d < 256; d <<= 1) {
        int x = (t >= d) ? s[t - d] : 0;
        __syncthreads();
        s[t] += x;
        __syncthreads();
    }
    if (t < SCAN_B) g_part[t] = s[t] - v;  // exclusive
}

__global__ void k_scan_final() {
    __shared__ int s[512];
    int i = blockIdx.x * 512 + threadIdx.x;
    int t = threadIdx.x;
    int v = (i < NENT) ? g_cnt[i] : 0;
    s[t] = v;
    __syncthreads();
    for (int d = 1; d < 512; d <<= 1) {
        int x = (t >= d) ? s[t - d] : 0;
        __syncthreads();
        s[t] += x;
        __syncthreads();
    }
    if (i < NENT) {
        int off = g_part[blockIdx.x] + s[t] - v;
        g_off[i] = off;
        g_cur[i] = off;
    }
}

__global__ void k_scatter(const float* __restrict__ enorm,
                          const int* __restrict__ src,
                          const int* __restrict__ dst,
                          const int* __restrict__ et) {
    int e = blockIdx.x * blockDim.x + threadIdx.x;
    if (e >= NEDGE) return;
    int d = dst[e];
    int pos = atomicAdd(&g_cur[d], 1);
    g_pay[pos] = make_float4(__int_as_float(src[e]), __int_as_float(et[e]),
                             enorm[e], 0.f);
}

// ---------------------------------------------------------------------------
// Aggregation: warp per dst, fp16 gathers, fp32 accumulate.
// Writes g_pre_frag (tf32 A-fragment layout).
// ---------------------------------------------------------------------------
__global__ void k_agg() {
    int gw = (blockIdx.x * blockDim.x + threadIdx.x) >> 5;
    int lane = threadIdx.x & 31;
    if (gw >= NENT) return;
    int cnt = g_cnt[gw];
    int off = g_off[gw];
    float4 acc = make_float4(0.f, 0.f, 0.f, 0.f);
    int i = 0;
    for (; i + 2 <= cnt; i += 2) {
        float4 p0 = g_pay[off + i];
        float4 p1 = g_pay[off + i + 1];
        int s0 = __float_as_int(p0.x), t0 = __float_as_int(p0.y);
        int s1 = __float_as_int(p1.x), t1 = __float_as_int(p1.y);
        uint2 h0 = g_hh[(size_t)s0 * 32 + lane];
        uint2 r0 = g_relh[(size_t)t0 * 32 + lane];
        uint2 h1 = g_hh[(size_t)s1 * 32 + lane];
        uint2 r1 = g_relh[(size_t)t1 * 32 + lane];
        float2 h0lo = __half22float2(*(__half2*)&h0.x);
        float2 h0hi = __half22float2(*(__half2*)&h0.y);
        float2 r0lo = __half22float2(*(__half2*)&r0.x);
        float2 r0hi = __half22float2(*(__half2*)&r0.y);
        float2 h1lo = __half22float2(*(__half2*)&h1.x);
        float2 h1hi = __half22float2(*(__half2*)&h1.y);
        float2 r1lo = __half22float2(*(__half2*)&r1.x);
        float2 r1hi = __half22float2(*(__half2*)&r1.y);
        acc.x += (h0lo.x + r0lo.x) * p0.z + (h1lo.x + r1lo.x) * p1.z;
        acc.y += (h0lo.y + r0lo.y) * p0.z + (h1lo.y + r1lo.y) * p1.z;
        acc.z += (h0hi.x + r0hi.x) * p0.z + (h1hi.x + r1hi.x) * p1.z;
        acc.w += (h0hi.y + r0hi.y) * p0.z + (h1hi.y + r1hi.y) * p1.z;
    }
    if (i < cnt) {
        float4 p0 = g_pay[off + i];
        int s0 = __float_as_int(p0.x), t0 = __float_as_int(p0.y);
        uint2 h0 = g_hh[(size_t)s0 * 32 + lane];
        uint2 r0 = g_relh[(size_t)t0 * 32 + lane];
        float2 h0lo = __half22float2(*(__half2*)&h0.x);
        float2 h0hi = __half22float2(*(__half2*)&h0.y);
        float2 r0lo = __half22float2(*(__half2*)&r0.x);
        float2 r0hi = __half22float2(*(__half2*)&r0.y);
        acc.x += (h0lo.x + r0lo.x) * p0.z;
        acc.y += (h0lo.y + r0lo.y) * p0.z;
        acc.z += (h0hi.x + r0hi.x) * p0.z;
        acc.w += (h0hi.y + r0hi.y) * p0.z;
    }
    int c0 = lane * 4;
    frag_store(g_pre_frag, gw, c0 + 0, acc.x);
    frag_store(g_pre_frag, gw, c0 + 1, acc.y);
    frag_store(g_pre_frag, gw, c0 + 2, acc.z);
    frag_store(g_pre_frag, gw, c0 + 3, acc.w);
}

// ---------------------------------------------------------------------------
// tf32 mma
// ---------------------------------------------------------------------------
__device__ __forceinline__ void mma_tf32(float c[4], unsigned a0, unsigned a1,
                                         unsigned a2, unsigned a3,
                                         unsigned b0, unsigned b1) {
    asm volatile(
        "mma.sync.aligned.m16n8k8.row.col.f32.tf32.tf32.f32 "
        "{%0,%1,%2,%3}, {%4,%5,%6,%7}, {%8,%9}, {%0,%1,%2,%3};"
        : "+f"(c[0]), "+f"(c[1]), "+f"(c[2]), "+f"(c[3])
        : "r"(a0), "r"(a1), "r"(a2), "r"(a3), "r"(b0), "r"(b1));
}

// ---------------------------------------------------------------------------
// GEMM1: h_cur = rrelu( [pre|h] @ [Wn;Ws] ). A from fragment buffers (uint4).
// ---------------------------------------------------------------------------
__global__ void __launch_bounds__(512, 1)
k_gemm1(const float* __restrict__ Wn, const float* __restrict__ Ws) {
    extern __shared__ unsigned sW[];  // 256 x PITCH
    for (int i = threadIdx.x; i < 256 * 128; i += blockDim.x) {
        int r = i >> 7, c = i & 127;
        float v = (r < 128) ? Wn[r * 128 + c] : Ws[(r - 128) * 128 + c];
        sW[r * PITCH + c] = f2tf(v);
    }
    __syncthreads();

    const int lane = threadIdx.x & 31;
    const int warp = threadIdx.x >> 5;
    const int g = lane >> 2, tig = lane & 3;
    const float SL = 0.22916666666666666f;
    const uint4* preF = (const uint4*)g_pre_frag;
    const uint4* hF = (const uint4*)g_h_frag;

    for (int tile = blockIdx.x * 16 + warp; tile < NTILE; tile += gridDim.x * 16) {
        int n0 = tile * 16;
        float acc[16][4];
#pragma unroll
        for (int nt = 0; nt < 16; nt++) {
            acc[nt][0] = 0.f; acc[nt][1] = 0.f; acc[nt][2] = 0.f; acc[nt][3] = 0.f;
        }

        for (int kk = 0; kk < 32; kk++) {
            int ks = kk & 15;
            const uint4* buf = (kk < 16) ? preF : hF;
            uint4 af = buf[(size_t)(tile * 16 + ks) * 32 + lane];
            const unsigned* bp = sW + (kk * 8 + tig) * PITCH + g;
#pragma unroll
            for (int nt = 0; nt < 16; nt++) {
                unsigned b0 = bp[nt * 8];
                unsigned b1 = bp[4 * PITCH + nt * 8];
                mma_tf32(acc[nt], af.x, af.y, af.z, af.w, b0, b1);
            }
        }

        float2* out = (float2*)g_hcur;
#pragma unroll
        for (int nt = 0; nt < 16; nt++) {
            float v0 = acc[nt][0], v1 = acc[nt][1], v2 = acc[nt][2], v3 = acc[nt][3];
            v0 = v0 >= 0.f ? v0 : SL * v0;
            v1 = v1 >= 0.f ? v1 : SL * v1;
            v2 = v2 >= 0.f ? v2 : SL * v2;
            v3 = v3 >= 0.f ? v3 : SL * v3;
            out[(size_t)(n0 + g) * 64 + nt * 4 + tig] = make_float2(v0, v1);
            out[(size_t)(n0 + 8 + g) * 64 + nt * 4 + tig] = make_float2(v2, v3);
            int cb = nt * 8 + 2 * tig;
            frag_store(g_hcur_frag, n0 + g,     cb,     v0);
            frag_store(g_hcur_frag, n0 + g,     cb + 1, v1);
            frag_store(g_hcur_frag, n0 + 8 + g, cb,     v2);
            frag_store(g_hcur_frag, n0 + 8 + g, cb + 1, v3);
        }
    }
}

// ---------------------------------------------------------------------------
// GEMM2 + gate: gate = sigmoid(h_cur @ Wg + b); out = gate*h_cur + (1-gate)*his
// ---------------------------------------------------------------------------
__global__ void __launch_bounds__(512, 1)
k_gemm2(const float* __restrict__ Wg, const float* __restrict__ bias,
        const float* __restrict__ his, float* __restrict__ outp) {
    extern __shared__ unsigned sW[];  // 128 x PITCH
    for (int i = threadIdx.x; i < 128 * 128; i += blockDim.x) {
        int r = i >> 7, c = i & 127;
        sW[r * PITCH + c] = f2tf(Wg[r * 128 + c]);
    }
    __syncthreads();

    const int lane = threadIdx.x & 31;
    const int warp = threadIdx.x >> 5;
    const int g = lane >> 2, tig = lane & 3;
    const uint4* hcF = (const uint4*)g_hcur_frag;

    float2 bs[16];
#pragma unroll
    for (int nt = 0; nt < 16; nt++)
        bs[nt] = ((const float2*)bias)[nt * 4 + tig];

    for (int tile = blockIdx.x * 16 + warp; tile < NTILE; tile += gridDim.x * 16) {
        int n0 = tile * 16;
        float acc[16][4];
#pragma unroll
        for (int nt = 0; nt < 16; nt++) {
            acc[nt][0] = 0.f; acc[nt][1] = 0.f; acc[nt][2] = 0.f; acc[nt][3] = 0.f;
        }

        for (int kk = 0; kk < 16; kk++) {
            uint4 af = hcF[(size_t)(tile * 16 + kk) * 32 + lane];
            const unsigned* bp = sW + (kk * 8 + tig) * PITCH + g;
#pragma unroll
            for (int nt = 0; nt < 16; nt++) {
                unsigned b0 = bp[nt * 8];
                unsigned b1 = bp[4 * PITCH + nt * 8];
                mma_tf32(acc[nt], af.x, af.y, af.z, af.w, b0, b1);
            }
        }

        const float2* hc2 = (const float2*)g_hcur;
        const float2* hs2 = (const float2*)his;
        float2* o2 = (float2*)outp;
#pragma unroll
        for (int nt = 0; nt < 16; nt++) {
            {
                size_t idx = (size_t)(n0 + g) * 64 + nt * 4 + tig;
                float2 hc = hc2[idx];
                float2 hs = hs2[idx];
                float gx = 1.0f / (1.0f + expf(-(acc[nt][0] + bs[nt].x)));
                float gy = 1.0f / (1.0f + expf(-(acc[nt][1] + bs[nt].y)));
                float2 o;
                o.x = fmaf(gx, hc.x - hs.x, hs.x);
                o.y = fmaf(gy, hc.y - hs.y, hs.y);
                o2[idx] = o;
            }
            {
                size_t idx = (size_t)(n0 + 8 + g) * 64 + nt * 4 + tig;
                float2 hc = hc2[idx];
                float2 hs = hs2[idx];
                float gx = 1.0f / (1.0f + expf(-(acc[nt][2] + bs[nt].x)));
                float gy = 1.0f / (1.0f + expf(-(acc[nt][3] + bs[nt].y)));
                float2 o;
                o.x = fmaf(gx, hc.x - hs.x, hs.x);
                o.y = fmaf(gy, hc.y - hs.y, hs.y);
                o2[idx] = o;
            }
        }
    }
}

// ---------------------------------------------------------------------------
// Launch
// ---------------------------------------------------------------------------
extern "C" void kernel_launch(void* const* d_in, const int* in_sizes, int n_in,
                              void* d_out, int out_size) {
    const float4* ent  = (const float4*)d_in[0];
    const float4* rel  = (const float4*)d_in[1];
    const float*  his  = (const float*)d_in[2];
    const float*  Wn   = (const float*)d_in[3];
    const float*  Ws   = (const float*)d_in[4];
    const float*  Wg   = (const float*)d_in[5];
    const float*  bias = (const float*)d_in[6];
    const float*  enorm = (const float*)d_in[7];
    const int*    src  = (const int*)d_in[8];
    const int*    dst  = (const int*)d_in[9];
    const int*    et   = (const int*)d_in[10];
    float* out = (float*)d_out;

    k_norm<<<(NENT * 32 + 255) / 256, 256>>>(ent);
    k_relh<<<(NREL * 32 + 255) / 256, 256>>>(rel);
    k_hist<<<(NEDGE + 511) / 512, 512>>>(dst);
    k_scan_part<<<SCAN_B, 512>>>();
    k_scan_top<<<1, 256>>>();
    k_scan_final<<<SCAN_B, 512>>>();
    k_scatter<<<(NEDGE + 511) / 512, 512>>>(enorm, src, dst, et);
    k_agg<<<(NENT * 32 + 511) / 512, 512>>>();
    {
        int smem = 256 * PITCH * 4;
        cudaFuncSetAttribute(k_gemm1, cudaFuncAttributeMaxDynamicSharedMemorySize, smem);
        k_gemm1<<<148, 512, smem>>>(Wn, Ws);
    }
    {
        int smem = 128 * PITCH * 4;
        cudaFuncSetAttribute(k_gemm2, cudaFuncAttributeMaxDynamicSharedMemorySize, smem);
        k_gemm2<<<148, 512, smem>>>(Wg, bias, his, out);
    }
}

// round 6
// speedup vs baseline: 3.8455x; 1.4343x over previous
#include <cuda_runtime.h>
#include <cuda_fp16.h>
#include <cstdint>

#define NENT 100000
#define NEDGE 2000000
#define NREL 1000
#define NTILE 6250          // NENT / 16
#define PITCH 136           // weight smem pitch (uint words): conflict-free B frags
#define SCAN_B 196          // ceil(NENT / 512)

// fused kernel block ranges (256 threads each)
#define NB_NORM 12500       // NENT*32/256
#define NB_REL  125         // NREL*32/256
#define NB_HIST 7813        // ceil(NEDGE/256)

// ---------------------------------------------------------------------------
// Scratch
// ---------------------------------------------------------------------------
__device__ uint2    g_hh[NENT * 32];          // normalized emb, fp16 row-major (8B/lane)
__device__ uint2    g_relh[NREL * 32];        // rel emb, fp16 row-major
__device__ unsigned g_h_frag[NENT * 64];      // normalized emb, fp16 mma-A frag (K=128)
__device__ unsigned g_pre_frag[NENT * 64];    // aggregation, fp16 A frag
__device__ unsigned g_hcur_frag[NENT * 64];   // hidden, fp16 A frag
__device__ float4   g_hcur[NENT * 32];        // hidden, fp32 row-major (epilogue)
__device__ uint2    g_pay[NEDGE];             // payload {src | et<<17, norm}
__device__ int g_cnt[NENT];
__device__ int g_off[NENT];
__device__ int g_cur[NENT];
__device__ int g_part[SCAN_B];

__device__ __forceinline__ unsigned packh2(float a, float b) {
    __half2 h = __floats2half2_rn(a, b);
    return *(unsigned*)&h;
}

// fp16 A-fragment (m16n8k16) store for node n, col pair base c0 = 4*lane:
//   word addr = ((t*8 + kk2)*32 + lane')*4 + j ; j = rowhalf + 2*khalf
__device__ __forceinline__ void frag16_store4(unsigned* buf, int n, int lane,
                                              float vx, float vy, float vz, float vw) {
    int t = n >> 4, lr = n & 15;
    int g = lr & 7, rh = lr >> 3;
    int kk2 = lane >> 2;
    int kh = (lane >> 1) & 1;
    int j = rh + 2 * kh;
    int lp0 = g * 4 + ((2 * lane) & 3);
    int lp1 = g * 4 + ((2 * lane + 1) & 3);
    size_t base = ((size_t)t * 8 + kk2) * 32;
    buf[(base + lp0) * 4 + j] = packh2(vx, vy);
    buf[(base + lp1) * 4 + j] = packh2(vz, vw);
}

// ---------------------------------------------------------------------------
// Kernel 1 (fused): norm -> g_hh + g_h_frag ; rel -> g_relh ; hist atomics.
// NOTE: g_cnt is re-zeroed by k_gemm1 at the END of each call (replay invariant).
// ---------------------------------------------------------------------------
__global__ void k_fused(const float4* __restrict__ ent,
                        const float4* __restrict__ rel,
                        const int* __restrict__ dst) {
    int b = blockIdx.x, t = threadIdx.x;
    if (b < NB_NORM) {
        int gw = (b * 256 + t) >> 5;
        int lane = t & 31;
        float4 v = ent[(size_t)gw * 32 + lane];
        float s = v.x * v.x + v.y * v.y + v.z * v.z + v.w * v.w;
#pragma unroll
        for (int o = 16; o; o >>= 1) s += __shfl_xor_sync(0xffffffffu, s, o);
        float inv = 1.0f / fmaxf(sqrtf(s), 1e-12f);
        v.x *= inv; v.y *= inv; v.z *= inv; v.w *= inv;
        g_hh[(size_t)gw * 32 + lane] = make_uint2(packh2(v.x, v.y), packh2(v.z, v.w));
        frag16_store4(g_h_frag, gw, lane, v.x, v.y, v.z, v.w);
    } else if (b < NB_NORM + NB_REL) {
        int gw = ((b - NB_NORM) * 256 + t) >> 5;
        int lane = t & 31;
        if (gw < NREL) {
            float4 v = rel[(size_t)gw * 32 + lane];
            g_relh[(size_t)gw * 32 + lane] = make_uint2(packh2(v.x, v.y), packh2(v.z, v.w));
        }
    } else {
        int e = (b - NB_NORM - NB_REL) * 256 + t;
        if (e < NEDGE) atomicAdd(&g_cnt[dst[e]], 1);
    }
}

// ---------------------------------------------------------------------------
// Scan (2 kernels)
// ---------------------------------------------------------------------------
__global__ void k_scan1() {
    int i = blockIdx.x * 512 + threadIdx.x;
    int v = (i < NENT) ? g_cnt[i] : 0;
    int lane = threadIdx.x & 31, wid = threadIdx.x >> 5;
#pragma unroll
    for (int o = 16; o; o >>= 1) v += __shfl_xor_sync(0xffffffffu, v, o);
    __shared__ int ws[16];
    if (lane == 0) ws[wid] = v;
    __syncthreads();
    if (threadIdx.x < 16) {
        int x = ws[threadIdx.x];
#pragma unroll
        for (int o = 8; o; o >>= 1) x += __shfl_xor_sync(0xffffu, x, o);
        if (threadIdx.x == 0) g_part[blockIdx.x] = x;
    }
}

__global__ void k_scan2() {
    __shared__ int sp[256];
    __shared__ int s[512];
    int t = threadIdx.x, b = blockIdx.x;
    if (t < 256) sp[t] = (t < SCAN_B) ? g_part[t] : 0;
    __syncthreads();
    for (int d = 1; d < 256; d <<= 1) {
        int x = 0;
        if (t < 256 && t >= d) x = sp[t - d];
        __syncthreads();
        if (t < 256) sp[t] += x;
        __syncthreads();
    }
    int base = (b == 0) ? 0 : sp[b - 1];
    int i = b * 512 + t;
    int v = (i < NENT) ? g_cnt[i] : 0;
    s[t] = v;
    __syncthreads();
    for (int d = 1; d < 512; d <<= 1) {
        int x = (t >= d) ? s[t - d] : 0;
        __syncthreads();
        s[t] += x;
        __syncthreads();
    }
    if (i < NENT) {
        int off = base + s[t] - v;
        g_off[i] = off;
        g_cur[i] = off;
    }
}

// ---------------------------------------------------------------------------
// Scatter: ticketed 8B payload
// ---------------------------------------------------------------------------
__global__ void k_scatter(const float* __restrict__ enorm,
                          const int* __restrict__ src,
                          const int* __restrict__ dst,
                          const int* __restrict__ et) {
    int e = blockIdx.x * blockDim.x + threadIdx.x;
    if (e >= NEDGE) return;
    int d = dst[e];
    int pos = atomicAdd(&g_cur[d], 1);
    g_pay[pos] = make_uint2((unsigned)src[e] | ((unsigned)et[e] << 17),
                            __float_as_uint(enorm[e]));
}

// ---------------------------------------------------------------------------
// Aggregation: warp per dst, fp16 gathers, fp32 accumulate, 4-wide MLP.
// ---------------------------------------------------------------------------
__device__ __forceinline__ void edge_acc(uint2 pv, int lane, float4& acc) {
    int s = pv.x & 0x1FFFF;
    int tt = pv.x >> 17;
    float w = __uint_as_float(pv.y);
    uint2 hv = g_hh[(size_t)s * 32 + lane];
    uint2 rv = g_relh[(size_t)tt * 32 + lane];
    float2 a = __half22float2(*(__half2*)&hv.x);
    float2 b = __half22float2(*(__half2*)&hv.y);
    float2 c = __half22float2(*(__half2*)&rv.x);
    float2 d = __half22float2(*(__half2*)&rv.y);
    acc.x = fmaf(a.x + c.x, w, acc.x);
    acc.y = fmaf(a.y + c.y, w, acc.y);
    acc.z = fmaf(b.x + d.x, w, acc.z);
    acc.w = fmaf(b.y + d.y, w, acc.w);
}

__global__ void k_agg() {
    int gw = (blockIdx.x * blockDim.x + threadIdx.x) >> 5;
    int lane = threadIdx.x & 31;
    if (gw >= NENT) return;
    int cnt = g_cnt[gw];
    int off = g_off[gw];
    float4 acc = make_float4(0.f, 0.f, 0.f, 0.f);
    int i = 0;
    for (; i + 4 <= cnt; i += 4) {
        uint2 p0 = g_pay[off + i];
        uint2 p1 = g_pay[off + i + 1];
        uint2 p2 = g_pay[off + i + 2];
        uint2 p3 = g_pay[off + i + 3];
        edge_acc(p0, lane, acc);
        edge_acc(p1, lane, acc);
        edge_acc(p2, lane, acc);
        edge_acc(p3, lane, acc);
    }
    for (; i < cnt; i++) {
        uint2 p0 = g_pay[off + i];
        edge_acc(p0, lane, acc);
    }
    frag16_store4(g_pre_frag, gw, lane, acc.x, acc.y, acc.z, acc.w);
}

// ---------------------------------------------------------------------------
// fp16 mma m16n8k16, fp32 accumulate
// ---------------------------------------------------------------------------
__device__ __forceinline__ void mma_f16(float c[4], uint4 a, unsigned b0, unsigned b1) {
    asm volatile(
        "mma.sync.aligned.m16n8k16.row.col.f32.f16.f16.f32 "
        "{%0,%1,%2,%3}, {%4,%5,%6,%7}, {%8,%9}, {%0,%1,%2,%3};"
        : "+f"(c[0]), "+f"(c[1]), "+f"(c[2]), "+f"(c[3])
        : "r"(a.x), "r"(a.y), "r"(a.z), "r"(a.w), "r"(b0), "r"(b1));
}

// ---------------------------------------------------------------------------
// GEMM1: h_cur = rrelu( [pre|h] @ [Wn;Ws] ), fp16 mma. Also re-zeroes g_cnt.
// Weights in smem as half2 pairs: sW[kp*PITCH + c] = (W[2kp][c], W[2kp+1][c]).
// ---------------------------------------------------------------------------
__global__ void __launch_bounds__(512, 1)
k_gemm1(const float* __restrict__ Wn, const float* __restrict__ Ws) {
    // replay invariant: leave g_cnt zeroed for the next call's histogram
    for (int i = blockIdx.x * 512 + threadIdx.x; i < NENT; i += gridDim.x * 512)
        g_cnt[i] = 0;

    extern __shared__ unsigned sW[];  // 128 x PITCH (half2 each)
    for (int i = threadIdx.x; i < 128 * 128; i += blockDim.x) {
        int kp = i >> 7, c = i & 127;
        int r0 = 2 * kp, r1 = r0 + 1;
        float v0 = (r0 < 128) ? Wn[r0 * 128 + c] : Ws[(r0 - 128) * 128 + c];
        float v1 = (r1 < 128) ? Wn[r1 * 128 + c] : Ws[(r1 - 128) * 128 + c];
        sW[kp * PITCH + c] = packh2(v0, v1);
    }
    __syncthreads();

    const int lane = threadIdx.x & 31;
    const int warp = threadIdx.x >> 5;
    const int g = lane >> 2, tig = lane & 3;
    const float SL = 0.22916666666666666f;
    const uint4* preF = (const uint4*)g_pre_frag;
    const uint4* hF = (const uint4*)g_h_frag;

    for (int tile = blockIdx.x * 16 + warp; tile < NTILE; tile += gridDim.x * 16) {
        int n0 = tile * 16;
        float acc[16][4];
#pragma unroll
        for (int nt = 0; nt < 16; nt++) {
            acc[nt][0] = 0.f; acc[nt][1] = 0.f; acc[nt][2] = 0.f; acc[nt][3] = 0.f;
        }

        for (int kk2 = 0; kk2 < 16; kk2++) {
            const uint4* buf = (kk2 < 8) ? preF : hF;
            int ks = kk2 & 7;
            uint4 af = buf[((size_t)tile * 8 + ks) * 32 + lane];
            const unsigned* bp = sW + (kk2 * 8 + tig) * PITCH + g;
#pragma unroll
            for (int nt = 0; nt < 16; nt++) {
                unsigned b0 = bp[nt * 8];
                unsigned b1 = bp[4 * PITCH + nt * 8];
                mma_f16(acc[nt], af, b0, b1);
            }
        }

        float2* out = (float2*)g_hcur;
#pragma unroll
        for (int nt = 0; nt < 16; nt++) {
            float v0 = acc[nt][0], v1 = acc[nt][1], v2 = acc[nt][2], v3 = acc[nt][3];
            v0 = v0 >= 0.f ? v0 : SL * v0;
            v1 = v1 >= 0.f ? v1 : SL * v1;
            v2 = v2 >= 0.f ? v2 : SL * v2;
            v3 = v3 >= 0.f ? v3 : SL * v3;
            out[(size_t)(n0 + g) * 64 + nt * 4 + tig] = make_float2(v0, v1);
            out[(size_t)(n0 + 8 + g) * 64 + nt * 4 + tig] = make_float2(v2, v3);
            // hcur frag16: row g   -> j = 2*(nt&1),   word half2(v0,v1)
            //              row g+8 -> j = 1+2*(nt&1), word half2(v2,v3)
            size_t base = ((size_t)tile * 8 + (nt >> 1)) * 32 + g * 4 + tig;
            g_hcur_frag[base * 4 + 2 * (nt & 1)]     = packh2(v0, v1);
            g_hcur_frag[base * 4 + 1 + 2 * (nt & 1)] = packh2(v2, v3);
        }
    }
}

// ---------------------------------------------------------------------------
// GEMM2 + gate: gate = sigmoid(h_cur @ Wg + b); out = gate*h_cur + (1-gate)*his
// ---------------------------------------------------------------------------
__global__ void __launch_bounds__(512, 1)
k_gemm2(const float* __restrict__ Wg, const float* __restrict__ bias,
        const float* __restrict__ his, float* __restrict__ outp) {
    extern __shared__ unsigned sW[];  // 64 x PITCH (half2 each)
    for (int i = threadIdx.x; i < 64 * 128; i += blockDim.x) {
        int kp = i >> 7, c = i & 127;
        sW[kp * PITCH + c] = packh2(Wg[(2 * kp) * 128 + c], Wg[(2 * kp + 1) * 128 + c]);
    }
    __syncthreads();

    const int lane = threadIdx.x & 31;
    const int warp = threadIdx.x >> 5;
    const int g = lane >> 2, tig = lane & 3;
    const uint4* hcF = (const uint4*)g_hcur_frag;

    float2 bs[16];
#pragma unroll
    for (int nt = 0; nt < 16; nt++)
        bs[nt] = ((const float2*)bias)[nt * 4 + tig];

    for (int tile = blockIdx.x * 16 + warp; tile < NTILE; tile += gridDim.x * 16) {
        int n0 = tile * 16;
        float acc[16][4];
#pragma unroll
        for (int nt = 0; nt < 16; nt++) {
            acc[nt][0] = 0.f; acc[nt][1] = 0.f; acc[nt][2] = 0.f; acc[nt][3] = 0.f;
        }

        for (int kk2 = 0; kk2 < 8; kk2++) {
            uint4 af = hcF[((size_t)tile * 8 + kk2) * 32 + lane];
            const unsigned* bp = sW + (kk2 * 8 + tig) * PITCH + g;
#pragma unroll
            for (int nt = 0; nt < 16; nt++) {
                unsigned b0 = bp[nt * 8];
                unsigned b1 = bp[4 * PITCH + nt * 8];
                mma_f16(acc[nt], af, b0, b1);
            }
        }

        const float2* hc2 = (const float2*)g_hcur;
        const float2* hs2 = (const float2*)his;
        float2* o2 = (float2*)outp;
#pragma unroll
        for (int nt = 0; nt < 16; nt++) {
            {
                size_t idx = (size_t)(n0 + g) * 64 + nt * 4 + tig;
                float2 hc = hc2[idx];
                float2 hs = hs2[idx];
                float gx = 1.0f / (1.0f + expf(-(acc[nt][0] + bs[nt].x)));
                float gy = 1.0f / (1.0f + expf(-(acc[nt][1] + bs[nt].y)));
                float2 o;
                o.x = fmaf(gx, hc.x - hs.x, hs.x);
                o.y = fmaf(gy, hc.y - hs.y, hs.y);
                o2[idx] = o;
            }
            {
                size_t idx = (size_t)(n0 + 8 + g) * 64 + nt * 4 + tig;
                float2 hc = hc2[idx];
                float2 hs = hs2[idx];
                float gx = 1.0f / (1.0f + expf(-(acc[nt][2] + bs[nt].x)));
                float gy = 1.0f / (1.0f + expf(-(acc[nt][3] + bs[nt].y)));
                float2 o;
                o.x = fmaf(gx, hc.x - hs.x, hs.x);
                o.y = fmaf(gy, hc.y - hs.y, hs.y);
                o2[idx] = o;
            }
        }
    }
}

// ---------------------------------------------------------------------------
// Launch: 7 kernels; #4 = k_scatter (profiled slot)
// ---------------------------------------------------------------------------
extern "C" void kernel_launch(void* const* d_in, const int* in_sizes, int n_in,
                              void* d_out, int out_size) {
    const float4* ent  = (const float4*)d_in[0];
    const float4* rel  = (const float4*)d_in[1];
    const float*  his  = (const float*)d_in[2];
    const float*  Wn   = (const float*)d_in[3];
    const float*  Ws   = (const float*)d_in[4];
    const float*  Wg   = (const float*)d_in[5];
    const float*  bias = (const float*)d_in[6];
    const float*  enorm = (const float*)d_in[7];
    const int*    src  = (const int*)d_in[8];
    const int*    dst  = (const int*)d_in[9];
    const int*    et   = (const int*)d_in[10];
    float* out = (float*)d_out;

    k_fused<<<NB_NORM + NB_REL + NB_HIST, 256>>>(ent, rel, dst);
    k_scan1<<<SCAN_B, 512>>>();
    k_scan2<<<SCAN_B, 512>>>();
    k_scatter<<<(NEDGE + 511) / 512, 512>>>(enorm, src, dst, et);
    k_agg<<<(NENT * 32 + 511) / 512, 512>>>();
    {
        int smem = 128 * PITCH * 4;
        cudaFuncSetAttribute(k_gemm1, cudaFuncAttributeMaxDynamicSharedMemorySize, smem);
        k_gemm1<<<148, 512, smem>>>(Wn, Ws);
    }
    {
        int smem = 64 * PITCH * 4;
        cudaFuncSetAttribute(k_gemm2, cudaFuncAttributeMaxDynamicSharedMemorySize, smem);
        k_gemm2<<<148, 512, smem>>>(Wg, bias, his, out);
    }
}